// round 1
// baseline (speedup 1.0000x reference)
#include <cuda_runtime.h>

#define NPTS 1600
#define CIN  256
#define ODIM 256
#define HD   64
#define NH   4
#define STR  68   // padded smem row stride (floats), multiple of 4 for LDS.128 alignment

__device__ __align__(16) float g_Q [NH*NPTS*HD];
__device__ __align__(16) float g_K [NH*NPTS*HD];
__device__ __align__(16) float g_V [NH*NPTS*HD];
__device__ __align__(16) float g_Vt[NH*NPTS*HD];
__device__ __align__(16) float g_part[16*NPTS*HD];

// ---------------------------------------------------------------------------
// QKV projection: out[head][n][d] = (xf @ W + b), xf = raw reshape of x.
// grid (25, 4, 3), block 256. BM=BN=64, BK=32, 4x4 micro-tiles.
// ---------------------------------------------------------------------------
__global__ __launch_bounds__(256) void proj_kernel(
    const float* __restrict__ x,
    const float* __restrict__ Wq, const float* __restrict__ bq,
    const float* __restrict__ Wk, const float* __restrict__ bk,
    const float* __restrict__ Wv, const float* __restrict__ bv)
{
    const float* W; const float* bias; float* out;
    if (blockIdx.z == 0)      { W = Wq; bias = bq; out = g_Q; }
    else if (blockIdx.z == 1) { W = Wk; bias = bk; out = g_K; }
    else                      { W = Wv; bias = bv; out = g_V; }

    __shared__ float sXT[32*STR];   // [c][n]  transposed
    __shared__ float sWt[32*STR];   // [c][o]  natural

    const int tid = threadIdx.x;
    const int tx = tid & 15, ty = tid >> 4;
    const int n0 = blockIdx.x * 64, o0 = blockIdx.y * 64;

    float acc[4][4] = {};

    for (int c0 = 0; c0 < CIN; c0 += 32) {
        #pragma unroll
        for (int it = 0; it < 2; it++) {
            int idx = tid + it*256;
            int r  = idx >> 3;            // n row 0..63
            int cc = (idx & 7) * 4;       // c col
            float4 v = *(const float4*)&x[(n0 + r)*CIN + c0 + cc];
            sXT[(cc+0)*STR + r] = v.x;
            sXT[(cc+1)*STR + r] = v.y;
            sXT[(cc+2)*STR + r] = v.z;
            sXT[(cc+3)*STR + r] = v.w;
        }
        #pragma unroll
        for (int it = 0; it < 2; it++) {
            int idx = tid + it*256;
            int r  = idx >> 4;            // c row 0..31
            int cc = (idx & 15) * 4;      // o col
            *(float4*)&sWt[r*STR + cc] = *(const float4*)&W[(c0 + r)*ODIM + o0 + cc];
        }
        __syncthreads();
        #pragma unroll 16
        for (int c = 0; c < 32; c++) {
            float4 a = *(float4*)&sXT[c*STR + ty*4];
            float4 b = *(float4*)&sWt[c*STR + tx*4];
            float av[4] = {a.x, a.y, a.z, a.w};
            float bv2[4] = {b.x, b.y, b.z, b.w};
            #pragma unroll
            for (int i = 0; i < 4; i++)
                #pragma unroll
                for (int j = 0; j < 4; j++)
                    acc[i][j] += av[i] * bv2[j];
        }
        __syncthreads();
    }

    #pragma unroll
    for (int j = 0; j < 4; j++) {
        int o = o0 + tx*4 + j;
        float bb = bias[o];
        int head = o >> 6, dd = o & 63;
        #pragma unroll
        for (int i = 0; i < 4; i++) {
            int n = n0 + ty*4 + i;
            out[(head*NPTS + n)*HD + dd] = acc[i][j] + bb;
        }
    }
}

// ---------------------------------------------------------------------------
// Vtilde[h][j][d] = sum_{s in {-4,-2,0,2,4}} V[h][(j+s) mod N][d]
// ---------------------------------------------------------------------------
__global__ __launch_bounds__(256) void vtilde_kernel()
{
    int idx4 = blockIdx.x * blockDim.x + threadIdx.x;   // 102400 float4s
    int e   = idx4 * 4;
    int h   = e / (NPTS*HD);
    int rem = e - h*(NPTS*HD);
    int j   = rem / HD;
    int dd  = rem - j*HD;

    float4 acc = make_float4(0.f, 0.f, 0.f, 0.f);
    #pragma unroll
    for (int s = -4; s <= 4; s += 2) {
        int jj = j + s;
        if (jj < 0) jj += NPTS;
        if (jj >= NPTS) jj -= NPTS;
        float4 v = *(const float4*)&g_V[(h*NPTS + jj)*HD + dd];
        acc.x += v.x; acc.y += v.y; acc.z += v.z; acc.w += v.w;
    }
    *(float4*)&g_Vt[(h*NPTS + j)*HD + dd] = acc;
}

// ---------------------------------------------------------------------------
// Flash attention, one (hq, kh) head pair per blockIdx.y, one 64-row Q tile
// per blockIdx.x. Full softmax over all 1600 keys of head kh, values from
// Vtilde of head vh, weight 2 for the folded h=+/-2 case.
// grid (25, 16), block 256, dynamic smem 4*64*STR floats.
// ---------------------------------------------------------------------------
__global__ __launch_bounds__(256) void attn_kernel()
{
    extern __shared__ float sm[];
    float* sQT = sm;               // [d][r]  (Q pre-scaled by 1/16)
    float* sKT = sm + 64*STR;      // [d][j]
    float* sV  = sm + 2*64*STR;    // [j][d]
    float* sPT = sm + 3*64*STR;    // [j][r]

    const int tid = threadIdx.x;
    const int tx = tid & 15, ty = tid >> 4;
    const int qn0 = blockIdx.x * 64;
    const int pair = blockIdx.y;
    const int hq = pair >> 2, kh = pair & 3;
    const int h  = ((hq - kh + 1) & 3) - 1;          // in {-1,0,1,2}
    const float wgt = (h == 2) ? 2.0f : 1.0f;        // h=+2 and h=-2 coincide
    const int vh = (hq + h + 4) & 3;

    // Load Q tile (scaled by 1/sqrt(O) = 1/16), transposed to d-major
    const float* Qb = g_Q + (hq*NPTS + qn0)*HD;
    #pragma unroll
    for (int it = 0; it < 4; it++) {
        int idx = tid + it*256;
        int r  = idx >> 4;
        int dd = (idx & 15) * 4;
        float4 v = *(const float4*)&Qb[r*HD + dd];
        sQT[(dd+0)*STR + r] = v.x * 0.0625f;
        sQT[(dd+1)*STR + r] = v.y * 0.0625f;
        sQT[(dd+2)*STR + r] = v.z * 0.0625f;
        sQT[(dd+3)*STR + r] = v.w * 0.0625f;
    }

    float m_i[4], l_i[4], oa[4][4];
    #pragma unroll
    for (int i = 0; i < 4; i++) {
        m_i[i] = -1e30f; l_i[i] = 0.f;
        #pragma unroll
        for (int j = 0; j < 4; j++) oa[i][j] = 0.f;
    }

    for (int kt = 0; kt < NPTS/64; kt++) {
        const float* Kb = g_K  + (kh*NPTS + kt*64)*HD;
        const float* Vb = g_Vt + (vh*NPTS + kt*64)*HD;
        #pragma unroll
        for (int it = 0; it < 4; it++) {
            int idx = tid + it*256;
            int r  = idx >> 4;
            int dd = (idx & 15) * 4;
            float4 kv = *(const float4*)&Kb[r*HD + dd];
            sKT[(dd+0)*STR + r] = kv.x;
            sKT[(dd+1)*STR + r] = kv.y;
            sKT[(dd+2)*STR + r] = kv.z;
            sKT[(dd+3)*STR + r] = kv.w;
            *(float4*)&sV[r*STR + dd] = *(const float4*)&Vb[r*HD + dd];
        }
        __syncthreads();

        // S = Qs @ K^T  (64x64x64)
        float s[4][4] = {};
        #pragma unroll 16
        for (int d = 0; d < 64; d++) {
            float4 a = *(float4*)&sQT[d*STR + ty*4];
            float4 b = *(float4*)&sKT[d*STR + tx*4];
            float av[4] = {a.x, a.y, a.z, a.w};
            float bv2[4] = {b.x, b.y, b.z, b.w};
            #pragma unroll
            for (int i = 0; i < 4; i++)
                #pragma unroll
                for (int j = 0; j < 4; j++)
                    s[i][j] += av[i] * bv2[j];
        }

        // Online softmax update (row reductions across 16 lanes via xor-shuffle)
        #pragma unroll
        for (int i = 0; i < 4; i++) {
            float tm = fmaxf(fmaxf(s[i][0], s[i][1]), fmaxf(s[i][2], s[i][3]));
            tm = fmaxf(tm, __shfl_xor_sync(0xffffffffu, tm, 1));
            tm = fmaxf(tm, __shfl_xor_sync(0xffffffffu, tm, 2));
            tm = fmaxf(tm, __shfl_xor_sync(0xffffffffu, tm, 4));
            tm = fmaxf(tm, __shfl_xor_sync(0xffffffffu, tm, 8));
            float mn = fmaxf(m_i[i], tm);
            float f  = __expf(m_i[i] - mn);
            m_i[i] = mn;
            float ps = 0.f;
            #pragma unroll
            for (int j = 0; j < 4; j++) {
                s[i][j] = __expf(s[i][j] - mn);
                ps += s[i][j];
            }
            ps += __shfl_xor_sync(0xffffffffu, ps, 1);
            ps += __shfl_xor_sync(0xffffffffu, ps, 2);
            ps += __shfl_xor_sync(0xffffffffu, ps, 4);
            ps += __shfl_xor_sync(0xffffffffu, ps, 8);
            l_i[i] = l_i[i]*f + ps;
            #pragma unroll
            for (int j = 0; j < 4; j++) oa[i][j] *= f;
        }

        // Stage P transposed ([j][r]) for the PV GEMM
        #pragma unroll
        for (int i = 0; i < 4; i++)
            #pragma unroll
            for (int j = 0; j < 4; j++)
                sPT[(tx*4 + j)*STR + ty*4 + i] = s[i][j];
        __syncthreads();

        // O += P @ Vtilde  (64x64x64)
        #pragma unroll 16
        for (int j = 0; j < 64; j++) {
            float4 a = *(float4*)&sPT[j*STR + ty*4];
            float4 b = *(float4*)&sV [j*STR + tx*4];
            float av[4] = {a.x, a.y, a.z, a.w};
            float bv2[4] = {b.x, b.y, b.z, b.w};
            #pragma unroll
            for (int i = 0; i < 4; i++)
                #pragma unroll
                for (int jj = 0; jj < 4; jj++)
                    oa[i][jj] += av[i] * bv2[jj];
        }
        __syncthreads();
    }

    float* op = g_part + (pair*NPTS + qn0)*HD;
    #pragma unroll
    for (int i = 0; i < 4; i++) {
        float inv = wgt / l_i[i];
        #pragma unroll
        for (int j = 0; j < 4; j++)
            op[(ty*4 + i)*HD + tx*4 + j] = oa[i][j] * inv;
    }
}

// ---------------------------------------------------------------------------
// out[n][hq*64+d] = sum_kh part[hq*4+kh][n][d]
// ---------------------------------------------------------------------------
__global__ __launch_bounds__(256) void combine_kernel(float* __restrict__ out)
{
    int idx4 = blockIdx.x * blockDim.x + threadIdx.x;   // 102400 float4s
    int e  = idx4 * 4;
    int n  = e >> 8;
    int o  = e & 255;
    int a  = o >> 6, dd = o & 63;
    float4 acc = make_float4(0.f, 0.f, 0.f, 0.f);
    #pragma unroll
    for (int khh = 0; khh < 4; khh++) {
        float4 v = *(const float4*)&g_part[((a*4 + khh)*NPTS + n)*HD + dd];
        acc.x += v.x; acc.y += v.y; acc.z += v.z; acc.w += v.w;
    }
    *(float4*)&out[e] = acc;
}

// ---------------------------------------------------------------------------
extern "C" void kernel_launch(void* const* d_in, const int* in_sizes, int n_in,
                              void* d_out, int out_size)
{
    const float* x  = (const float*)d_in[0];
    const float* Wq = (const float*)d_in[1];
    const float* bq = (const float*)d_in[2];
    const float* Wk = (const float*)d_in[3];
    const float* bk = (const float*)d_in[4];
    const float* Wv = (const float*)d_in[5];
    const float* bv = (const float*)d_in[6];
    float* out = (float*)d_out;

    const int smem_bytes = 4*64*STR*(int)sizeof(float);   // 69632
    cudaFuncSetAttribute(attn_kernel,
                         cudaFuncAttributeMaxDynamicSharedMemorySize, smem_bytes);

    proj_kernel<<<dim3(NPTS/64, ODIM/64, 3), 256>>>(x, Wq, bq, Wk, bk, Wv, bv);
    vtilde_kernel<<<(NH*NPTS*HD/4 + 255)/256, 256>>>();
    attn_kernel<<<dim3(NPTS/64, 16), 256, smem_bytes>>>();
    combine_kernel<<<(NPTS*ODIM/4 + 255)/256, 256>>>(out);
}